// round 8
// baseline (speedup 1.0000x reference)
#include <cuda_runtime.h>
#include <cstdint>

#define B_  8
#define N_  4096
#define L_  4096
#define GC_ 32
#define IC_ 256

__device__ uint32_t g_Qb [B_*N_*16];      // [b][n][k2] bf16x2 (Q*QSCALE)
__device__ uint32_t g_Kb [B_*L_*16];      // [b][l][k2] bf16x2
__device__ float    g_VTc[B_*GC_*L_];     // [b][c][l] raw f32 (channel-major)
__device__ uint32_t g_Vb [B_*GC_*(L_/2)]; // [b][c][l2] bf16x2 of V*Dinv
__device__ float    g_Dp [2][B_*L_];      // partial exp-sums (n-split halves)
__device__ float    g_Mp [2][B_*N_*GC_];  // partial msg (l-split halves)

#define QSCALE 0.2550668292560464f  // (1/sqrt(32)) * log2(e)

// ===========================================================================
// helpers
// ===========================================================================
__device__ __forceinline__ uint32_t smem_u32(const void* p) {
    uint32_t a;
    asm("{ .reg .u64 t; cvta.to.shared.u64 t, %1; cvt.u32.u64 %0, t; }"
        : "=r"(a) : "l"(p));
    return a;
}
__device__ __forceinline__ float ex2f(float x) {
    float y;
    asm("ex2.approx.f32 %0, %1;" : "=f"(y) : "f"(x));
    return y;
}
__device__ __forceinline__ uint32_t pk_bf16x2(float hi, float lo) {
    uint32_t r;
    asm("cvt.rn.bf16x2.f32 %0, %1, %2;" : "=r"(r) : "f"(hi), "f"(lo));
    return r;
}
__device__ __forceinline__ void mma_bf16(float c[4], const uint32_t a[4],
                                         uint32_t b0, uint32_t b1) {
    asm volatile("mma.sync.aligned.m16n8k16.row.col.f32.bf16.bf16.f32 "
        "{%0,%1,%2,%3}, {%4,%5,%6,%7}, {%8,%9}, {%0,%1,%2,%3};"
        : "+f"(c[0]), "+f"(c[1]), "+f"(c[2]), "+f"(c[3])
        : "r"(a[0]), "r"(a[1]), "r"(a[2]), "r"(a[3]), "r"(b0), "r"(b1));
}
__device__ __forceinline__ void cp16(uint32_t s, const void* g) {
    asm volatile("cp.async.ca.shared.global [%0], [%1], 16;"
                 :: "r"(s), "l"(g) : "memory");
}
#define CP_COMMIT() asm volatile("cp.async.commit_group;" ::: "memory")
#define CP_WAIT1()  asm volatile("cp.async.wait_group 1;" ::: "memory")
#define CP_WAIT0()  asm volatile("cp.async.wait_group 0;" ::: "memory")

// ===========================================================================
// Kernel 1: Q projection (SIMT, tiny) -> packed bf16x2, QSCALE folded
// ===========================================================================
__global__ __launch_bounds__(256) void k_proj_q(
    const float* __restrict__ graph, const float* __restrict__ Wq,
    const float* __restrict__ bq)
{
    __shared__ float WqS[GC_*33];
    __shared__ float gS[64*GC_];
    int b  = blockIdx.x >> 6;
    int n0 = (blockIdx.x & 63) * 64;
    int tid = threadIdx.x;

    for (int i = tid; i < GC_*GC_; i += 256)
        WqS[(i>>5)*33 + (i&31)] = Wq[i];
    const float* gp = graph + ((long)b*N_ + n0)*GC_;
    for (int i = tid; i < 64*GC_; i += 256) gS[i] = gp[i];
    __syncthreads();

    int o2 = tid & 15, nb = tid >> 4;
    float b0 = bq[2*o2], b1 = bq[2*o2 + 1];
    #pragma unroll
    for (int j = 0; j < 4; j++) {
        int n = nb + 16*j;
        float a0 = b0, a1 = b1;
        #pragma unroll
        for (int c = 0; c < 32; c++) {
            float gv = gS[n*32 + c];
            a0 += WqS[(2*o2    )*33 + c] * gv;
            a1 += WqS[(2*o2 + 1)*33 + c] * gv;
        }
        g_Qb[((long)b*N_ + n0 + n)*16 + o2] = pk_bf16x2(a1*QSCALE, a0*QSCALE);
    }
}

// ===========================================================================
// Kernel 2: K/V projection via bf16 MMA (unchanged from R6/R7).
// ===========================================================================
#define PW 132
#define PI 260

__global__ __launch_bounds__(256, 1) void k_proj_kv_mma(
    const float* __restrict__ img,
    const float* __restrict__ Wk, const float* __restrict__ bk,
    const float* __restrict__ Wv, const float* __restrict__ bv)
{
    extern __shared__ uint32_t shm[];
    uint32_t* Wsm  = shm;
    float*    img0 = (float*)(shm + 64*PW);
    float*    img1 = img0 + 64*PI;

    int tid = threadIdx.x, w = tid >> 5, lane = tid & 31;
    int q = lane & 3, g = lane >> 2;
    int b = blockIdx.x >> 4, l0 = (blockIdx.x & 15) * 256;

    #pragma unroll
    for (int t = 0; t < 32; t++) {
        int u = tid + t*256;
        int o = u >> 7, c2 = u & 127;
        const float* src = (o < 32) ? (Wk + o*IC_ + 2*c2) : (Wv + (o-32)*IC_ + 2*c2);
        float2 v = *(const float2*)src;
        Wsm[o*PW + c2] = pk_bf16x2(v.y, v.x);
    }

    auto pref = [&](int ks, float* dstbuf) {
        const float* src = img + ((long)b*IC_ + ks*64)*L_ + l0;
        uint32_t dstb = smem_u32(dstbuf);
        #pragma unroll
        for (int t = 0; t < 16; t++) {
            int u = tid + t*256;
            int c = u >> 6, col = (u & 63) * 4;
            cp16(dstb + (c*PI + col)*4, src + (long)c*L_ + col);
        }
        CP_COMMIT();
    };
    pref(0, img0);

    float C[4][4][4];
    #pragma unroll
    for (int mt = 0; mt < 4; mt++) {
        const float* bias = (mt < 2) ? bk : bv;
        int ob = (mt & 1) * 16;
        float blo = bias[ob + g], bhi = bias[ob + 8 + g];
        #pragma unroll
        for (int nt = 0; nt < 4; nt++) {
            C[mt][nt][0] = C[mt][nt][1] = blo;
            C[mt][nt][2] = C[mt][nt][3] = bhi;
        }
    }
    __syncthreads();

    int lw = w * 32;
    for (int ks = 0; ks < 4; ks++) {
        if (ks < 3) { pref(ks + 1, (ks & 1) ? img0 : img1); CP_WAIT1(); }
        else CP_WAIT0();
        __syncthreads();
        const float* I = (ks & 1) ? img1 : img0;
        #pragma unroll
        for (int kk = 0; kk < 4; kk++) {
            uint32_t A[4][4];
            #pragma unroll
            for (int mt = 0; mt < 4; mt++) {
                const uint32_t* wp = Wsm + (mt*16)*PW + ks*32 + kk*8;
                A[mt][0] = wp[ g   *PW + q];
                A[mt][1] = wp[(g+8)*PW + q];
                A[mt][2] = wp[ g   *PW + q + 4];
                A[mt][3] = wp[(g+8)*PW + q + 4];
            }
            uint32_t Bf[4][2];
            #pragma unroll
            for (int nt = 0; nt < 4; nt++) {
                int l = lw + nt*8 + g;
                const float* r0 = I + (kk*16 + 2*q    )*PI + l;
                const float* r1 = I + (kk*16 + 2*q + 8)*PI + l;
                Bf[nt][0] = pk_bf16x2(r0[PI], r0[0]);
                Bf[nt][1] = pk_bf16x2(r1[PI], r1[0]);
            }
            #pragma unroll
            for (int mt = 0; mt < 4; mt++)
                #pragma unroll
                for (int nt = 0; nt < 4; nt++)
                    mma_bf16(C[mt][nt], A[mt], Bf[nt][0], Bf[nt][1]);
        }
        __syncthreads();
    }

    bool odd = (g & 1);
    int sA = 8*q + (g >> 1), sB = sA + 4;
    #pragma unroll
    for (int mt = 0; mt < 2; mt++)
        #pragma unroll
        for (int nt = 0; nt < 4; nt++) {
            float* c = C[mt][nt];
            float t0 = __shfl_sync(~0u, c[0], sA), t1 = __shfl_sync(~0u, c[1], sA);
            float t2 = __shfl_sync(~0u, c[0], sB), t3 = __shfl_sync(~0u, c[1], sB);
            float t4 = __shfl_sync(~0u, c[2], sA), t5 = __shfl_sync(~0u, c[3], sA);
            float t6 = __shfl_sync(~0u, c[2], sB), t7 = __shfl_sync(~0u, c[3], sB);
            float lo0 = odd ? t1 : t0, hi0 = odd ? t3 : t2;
            float lo1 = odd ? t5 : t4, hi1 = odd ? t7 : t6;
            long l = (long)b*L_ + l0 + lw + nt*8 + g;
            g_Kb[l*16 + mt*8 + q    ] = pk_bf16x2(hi0, lo0);
            g_Kb[l*16 + mt*8 + 4 + q] = pk_bf16x2(hi1, lo1);
        }
    #pragma unroll
    for (int mt = 2; mt < 4; mt++)
        #pragma unroll
        for (int nt = 0; nt < 4; nt++) {
            int c = (mt - 2)*16 + g;
            long base = ((long)b*GC_ + c)*L_ + l0 + lw + nt*8 + 2*q;
            *(float2*)(g_VTc + base)         = make_float2(C[mt][nt][0], C[mt][nt][1]);
            *(float2*)(g_VTc + base + 8*L_)  = make_float2(C[mt][nt][2], C[mt][nt][3]);
        }
}

// ===========================================================================
// Kernel 3: stats, n-split. grid = B*16*2 = 256; CTA does 2048 n.
// Writes partial d to g_Dp[half].
// ===========================================================================
#define QP 20

__global__ __launch_bounds__(256, 2) void k_stats_mma()
{
    __shared__ __align__(16) uint32_t Qs[2][128*QP];
    int tid = threadIdx.x, w = tid >> 5, lane = tid & 31;
    int q = lane & 3, g = lane >> 2;
    int bi = blockIdx.x;
    int b = bi >> 5, l0 = ((bi >> 1) & 15) * 256, half = bi & 1;
    uint32_t qs_b = smem_u32(Qs);

    uint32_t A[2][2][4];
    #pragma unroll
    for (int mt = 0; mt < 2; mt++) {
        const uint32_t* kp = g_Kb + ((long)b*L_ + l0 + w*32 + mt*16)*16;
        #pragma unroll
        for (int kk = 0; kk < 2; kk++) {
            A[mt][kk][0] = kp[ g   *16 + 8*kk + q    ];
            A[mt][kk][1] = kp[(g+8)*16 + 8*kk + q    ];
            A[mt][kk][2] = kp[ g   *16 + 8*kk + q + 4];
            A[mt][kk][3] = kp[(g+8)*16 + 8*kk + q + 4];
        }
    }

    auto prefetch = [&](int nc, int buf) {
        const uint32_t* src = g_Qb + ((long)b*N_ + nc*128)*16;
        #pragma unroll
        for (int it = 0; it < 2; it++) {
            int i = tid + it*256;
            int r = i >> 2, t = i & 3;
            cp16(qs_b + (buf*128*QP + r*QP + 4*t)*4, src + r*16 + 4*t);
        }
        CP_COMMIT();
    };
    int nc0 = half*16, nc1 = nc0 + 16;
    prefetch(nc0, nc0 & 1);

    float d[2][2] = {{0.f,0.f},{0.f,0.f}};
    for (int nc = nc0; nc < nc1; nc++) {
        if (nc < nc1 - 1) { prefetch(nc + 1, (nc + 1) & 1); CP_WAIT1(); }
        else CP_WAIT0();
        __syncthreads();
        const uint32_t* Q = &Qs[nc & 1][0];
        #pragma unroll 4
        for (int j = 0; j < 16; j++) {
            const uint32_t* bp = &Q[(g + 8*j)*QP + q];
            uint32_t b00 = bp[0], b01 = bp[4];
            uint32_t b10 = bp[8], b11 = bp[12];
            #pragma unroll
            for (int mt = 0; mt < 2; mt++) {
                float c[4] = {0.f, 0.f, 0.f, 0.f};
                mma_bf16(c, A[mt][0], b00, b01);
                mma_bf16(c, A[mt][1], b10, b11);
                d[mt][0] += ex2f(c[0]) + ex2f(c[1]);
                d[mt][1] += ex2f(c[2]) + ex2f(c[3]);
            }
        }
        __syncthreads();
    }
    #pragma unroll
    for (int mt = 0; mt < 2; mt++) {
        #pragma unroll
        for (int h = 0; h < 2; h++) {
            float dv = d[mt][h];
            dv += __shfl_xor_sync(~0u, dv, 1);
            dv += __shfl_xor_sync(~0u, dv, 2);
            if (q == 0)
                g_Dp[half][(long)b*L_ + l0 + w*32 + mt*16 + h*8 + g] = dv;
        }
    }
}

// ===========================================================================
// Kernel 3b: combine d halves -> Dinv, pack V' = V*Dinv into g_Vb.
// grid 256 x 256 threads, 8 elems each over [B][GC][L/2].
// ===========================================================================
__global__ __launch_bounds__(256) void k_vpack()
{
    int base = blockIdx.x * 2048 + threadIdx.x;
    #pragma unroll
    for (int it = 0; it < 8; it++) {
        int u = base + it*256;
        int b = u >> 16, c = (u >> 11) & 31, l2 = u & 2047;
        long dl = (long)b*L_ + 2*l2;
        float dlo = g_Dp[0][dl]     + g_Dp[1][dl];
        float dhi = g_Dp[0][dl + 1] + g_Dp[1][dl + 1];
        const float* vp = g_VTc + ((long)b*GC_ + c)*L_ + 2*l2;
        float2 v = *(const float2*)vp;
        g_Vb[((long)b*GC_ + c)*(L_/2) + l2] =
            pk_bf16x2(v.y / dhi, v.x / dlo);
    }
}

// ===========================================================================
// Kernel 4: final, l-split. grid = B*16*2 = 256; CTA does 2048 l.
// Writes partial raw msg to g_Mp[half].
// ===========================================================================
#define KP 20
#define VP 68

__global__ __launch_bounds__(256, 2) void k_final_mma()
{
    __shared__ __align__(16) uint32_t Ks[2][128*KP];
    __shared__ __align__(16) uint32_t Vbs[2][32*VP];
    int tid = threadIdx.x, w = tid >> 5, lane = tid & 31;
    int q = lane & 3, g = lane >> 2;
    int bi = blockIdx.x;
    int b = bi >> 5, n0 = ((bi >> 1) & 15) * 256, half = bi & 1;
    uint32_t ks_b = smem_u32(Ks), vb_b = smem_u32(Vbs);

    uint32_t A[2][2][4];
    #pragma unroll
    for (int mt = 0; mt < 2; mt++) {
        const uint32_t* qp = g_Qb + ((long)b*N_ + n0 + w*32 + mt*16)*16;
        #pragma unroll
        for (int kk = 0; kk < 2; kk++) {
            A[mt][kk][0] = qp[ g   *16 + 8*kk + q    ];
            A[mt][kk][1] = qp[(g+8)*16 + 8*kk + q    ];
            A[mt][kk][2] = qp[ g   *16 + 8*kk + q + 4];
            A[mt][kk][3] = qp[(g+8)*16 + 8*kk + q + 4];
        }
    }

    const uint32_t* vbsrc = g_Vb + ((long)b*GC_)*(L_/2);
    auto prefetch = [&](int lc, int buf) {
        const uint32_t* ksrc = g_Kb + ((long)b*L_ + lc*128)*16;
        #pragma unroll
        for (int it = 0; it < 2; it++) {
            int i = tid + it*256;
            int r = i >> 2, t = i & 3;
            cp16(ks_b + (buf*128*KP + r*KP + 4*t)*4, ksrc + r*16 + 4*t);
        }
        #pragma unroll
        for (int it = 0; it < 2; it++) {
            int i = tid + it*256;
            int c = i >> 4, t2 = i & 15;
            cp16(vb_b + (buf*32*VP + c*VP + 4*t2)*4,
                 vbsrc + (long)c*(L_/2) + lc*64 + 4*t2);
        }
        CP_COMMIT();
    };
    int lc0 = half*16, lc1 = lc0 + 16;
    prefetch(lc0, lc0 & 1);

    float mc[2][4][4];
    #pragma unroll
    for (int mt = 0; mt < 2; mt++)
        #pragma unroll
        for (int cf = 0; cf < 4; cf++)
            #pragma unroll
            for (int x = 0; x < 4; x++) mc[mt][cf][x] = 0.f;

    for (int lc = lc0; lc < lc1; lc++) {
        if (lc < lc1 - 1) { prefetch(lc + 1, (lc + 1) & 1); CP_WAIT1(); }
        else CP_WAIT0();
        __syncthreads();
        const uint32_t* K = &Ks[lc & 1][0];
        const uint32_t* V = &Vbs[lc & 1][0];

        #pragma unroll 2
        for (int s = 0; s < 8; s++) {
            const uint32_t* bpa = &K[(g + 16*s    )*KP + q];
            const uint32_t* bpb = &K[(g + 16*s + 8)*KP + q];
            uint32_t ba00 = bpa[0], ba01 = bpa[4], ba10 = bpa[8], ba11 = bpa[12];
            uint32_t bb00 = bpb[0], bb01 = bpb[4], bb10 = bpb[8], bb11 = bpb[12];
            uint32_t vb0[4], vb1[4];
            #pragma unroll
            for (int cf = 0; cf < 4; cf++) {
                vb0[cf] = V[(g + 8*cf)*VP + 8*s + q    ];
                vb1[cf] = V[(g + 8*cf)*VP + 8*s + q + 4];
            }
            #pragma unroll
            for (int mt = 0; mt < 2; mt++) {
                float c0[4] = {0.f,0.f,0.f,0.f};
                float c1[4] = {0.f,0.f,0.f,0.f};
                mma_bf16(c0, A[mt][0], ba00, ba01);
                mma_bf16(c0, A[mt][1], ba10, ba11);
                mma_bf16(c1, A[mt][0], bb00, bb01);
                mma_bf16(c1, A[mt][1], bb10, bb11);
                uint32_t A2[4];
                A2[0] = pk_bf16x2(ex2f(c0[1]), ex2f(c0[0]));
                A2[1] = pk_bf16x2(ex2f(c0[3]), ex2f(c0[2]));
                A2[2] = pk_bf16x2(ex2f(c1[1]), ex2f(c1[0]));
                A2[3] = pk_bf16x2(ex2f(c1[3]), ex2f(c1[2]));
                #pragma unroll
                for (int cf = 0; cf < 4; cf++)
                    mma_bf16(mc[mt][cf], A2, vb0[cf], vb1[cf]);
            }
        }
        __syncthreads();
    }

    // store partial msg
    #pragma unroll
    for (int mt = 0; mt < 2; mt++) {
        long nbase = (long)b*N_ + n0 + w*32 + mt*16;
        #pragma unroll
        for (int cf = 0; cf < 4; cf++) {
            int col = cf*8 + 2*q;
            *(float2*)&g_Mp[half][(nbase + g    )*32 + col] =
                make_float2(mc[mt][cf][0], mc[mt][cf][1]);
            *(float2*)&g_Mp[half][(nbase + g + 8)*32 + col] =
                make_float2(mc[mt][cf][2], mc[mt][cf][3]);
        }
    }
}

// ===========================================================================
// Kernel 5: combine msg halves + Wc GEMM + residual.
// grid = B*(N/64) = 512, 256 threads.
// ===========================================================================
__global__ __launch_bounds__(256) void k_out(
    const float* __restrict__ graph, const float* __restrict__ Wc,
    const float* __restrict__ bc, float* __restrict__ out)
{
    __shared__ float WcS[GC_*33];
    __shared__ float mS[64*33];
    int b  = blockIdx.x >> 6;
    int n0 = (blockIdx.x & 63) * 64;
    int tid = threadIdx.x;

    for (int i = tid; i < GC_*GC_; i += 256)
        WcS[(i>>5)*33 + (i&31)] = Wc[i];
    long base = ((long)b*N_ + n0)*GC_;
    for (int i = tid; i < 64*GC_; i += 256)
        mS[(i>>5)*33 + (i&31)] = g_Mp[0][base + i] + g_Mp[1][base + i];
    __syncthreads();

    int o = tid & 31, nb = tid >> 5;
    const float* gp = graph + base;
    float bias = bc[o];
    #pragma unroll
    for (int j = 0; j < 8; j++) {
        int n = nb + j*8;
        float acc = bias;
        #pragma unroll
        for (int c = 0; c < 32; c++) acc += WcS[o*33+c] * mS[n*33+c];
        out[base + n*GC_ + o] = gp[n*GC_ + o] + acc;
    }
}

// ===========================================================================
extern "C" void kernel_launch(void* const* d_in, const int* in_sizes, int n_in,
                              void* d_out, int out_size)
{
    const float* graph = (const float*)d_in[0];
    const float* img   = (const float*)d_in[1];
    const float* Wq    = (const float*)d_in[2];
    const float* bq    = (const float*)d_in[3];
    const float* Wk    = (const float*)d_in[4];
    const float* bk    = (const float*)d_in[5];
    const float* Wv    = (const float*)d_in[6];
    const float* bv    = (const float*)d_in[7];
    const float* Wc    = (const float*)d_in[8];
    const float* bc    = (const float*)d_in[9];
    float* out = (float*)d_out;

    size_t proj_smem = (64*PW + 2*64*PI) * sizeof(uint32_t);
    static int attr_set = 0;
    if (!attr_set) {
        cudaFuncSetAttribute(k_proj_kv_mma,
                             cudaFuncAttributeMaxDynamicSharedMemorySize,
                             (int)proj_smem);
        attr_set = 1;
    }

    k_proj_q     <<<B_*(N_/64), 256>>>(graph, Wq, bq);
    k_proj_kv_mma<<<B_*(L_/256), 256, proj_smem>>>(img, Wk, bk, Wv, bv);
    k_stats_mma  <<<B_*(L_/256)*2, 256>>>();
    k_vpack      <<<256, 256>>>();
    k_final_mma  <<<B_*(N_/256)*2, 256>>>();
    k_out        <<<B_*(N_/64), 256>>>(graph, Wc, bc, out);
}

// round 9
// speedup vs baseline: 1.0352x; 1.0352x over previous
#include <cuda_runtime.h>
#include <cstdint>

#define B_  8
#define N_  4096
#define L_  4096
#define GC_ 32
#define IC_ 256

__device__ uint32_t g_Qb [B_*N_*16];      // [b][n][k2] bf16x2 (Q*QSCALE)
__device__ uint32_t g_Kb [B_*L_*16];      // [b][l][k2] bf16x2
__device__ float    g_VTc[B_*GC_*L_];     // [b][c][l] raw f32 (channel-major)
__device__ uint32_t g_Vb [B_*GC_*(L_/2)]; // [b][c][l2] bf16x2 of V*Dinv

#define QSCALE 0.2550668292560464f  // (1/sqrt(32)) * log2(e)

// ===========================================================================
// helpers
// ===========================================================================
__device__ __forceinline__ uint32_t smem_u32(const void* p) {
    uint32_t a;
    asm("{ .reg .u64 t; cvta.to.shared.u64 t, %1; cvt.u32.u64 %0, t; }"
        : "=r"(a) : "l"(p));
    return a;
}
__device__ __forceinline__ float ex2f(float x) {
    float y;
    asm("ex2.approx.f32 %0, %1;" : "=f"(y) : "f"(x));
    return y;
}
__device__ __forceinline__ uint32_t pk_bf16x2(float hi, float lo) {
    uint32_t r;
    asm("cvt.rn.bf16x2.f32 %0, %1, %2;" : "=r"(r) : "f"(hi), "f"(lo));
    return r;
}
__device__ __forceinline__ void mma_bf16(float c[4], const uint32_t a[4],
                                         uint32_t b0, uint32_t b1) {
    asm volatile("mma.sync.aligned.m16n8k16.row.col.f32.bf16.bf16.f32 "
        "{%0,%1,%2,%3}, {%4,%5,%6,%7}, {%8,%9}, {%0,%1,%2,%3};"
        : "+f"(c[0]), "+f"(c[1]), "+f"(c[2]), "+f"(c[3])
        : "r"(a[0]), "r"(a[1]), "r"(a[2]), "r"(a[3]), "r"(b0), "r"(b1));
}
__device__ __forceinline__ void cp16(uint32_t s, const void* g) {
    asm volatile("cp.async.ca.shared.global [%0], [%1], 16;"
                 :: "r"(s), "l"(g) : "memory");
}
#define CP_COMMIT() asm volatile("cp.async.commit_group;" ::: "memory")
#define CP_WAIT1()  asm volatile("cp.async.wait_group 1;" ::: "memory")
#define CP_WAIT0()  asm volatile("cp.async.wait_group 0;" ::: "memory")

// ===========================================================================
// Kernel 1: Q projection (SIMT, tiny) -> packed bf16x2, QSCALE folded
// ===========================================================================
__global__ __launch_bounds__(256) void k_proj_q(
    const float* __restrict__ graph, const float* __restrict__ Wq,
    const float* __restrict__ bq)
{
    __shared__ float WqS[GC_*33];
    __shared__ float gS[64*GC_];
    int b  = blockIdx.x >> 6;
    int n0 = (blockIdx.x & 63) * 64;
    int tid = threadIdx.x;

    for (int i = tid; i < GC_*GC_; i += 256)
        WqS[(i>>5)*33 + (i&31)] = Wq[i];
    const float* gp = graph + ((long)b*N_ + n0)*GC_;
    for (int i = tid; i < 64*GC_; i += 256) gS[i] = gp[i];
    __syncthreads();

    int o2 = tid & 15, nb = tid >> 4;
    float b0 = bq[2*o2], b1 = bq[2*o2 + 1];
    #pragma unroll
    for (int j = 0; j < 4; j++) {
        int n = nb + 16*j;
        float a0 = b0, a1 = b1;
        #pragma unroll
        for (int c = 0; c < 32; c++) {
            float gv = gS[n*32 + c];
            a0 += WqS[(2*o2    )*33 + c] * gv;
            a1 += WqS[(2*o2 + 1)*33 + c] * gv;
        }
        g_Qb[((long)b*N_ + n0 + n)*16 + o2] = pk_bf16x2(a1*QSCALE, a0*QSCALE);
    }
}

// ===========================================================================
// Kernel 2: K/V projection via bf16 MMA (unchanged).
// ===========================================================================
#define PW 132
#define PI 260

__global__ __launch_bounds__(256, 1) void k_proj_kv_mma(
    const float* __restrict__ img,
    const float* __restrict__ Wk, const float* __restrict__ bk,
    const float* __restrict__ Wv, const float* __restrict__ bv)
{
    extern __shared__ uint32_t shm[];
    uint32_t* Wsm  = shm;
    float*    img0 = (float*)(shm + 64*PW);
    float*    img1 = img0 + 64*PI;

    int tid = threadIdx.x, w = tid >> 5, lane = tid & 31;
    int q = lane & 3, g = lane >> 2;
    int b = blockIdx.x >> 4, l0 = (blockIdx.x & 15) * 256;

    #pragma unroll
    for (int t = 0; t < 32; t++) {
        int u = tid + t*256;
        int o = u >> 7, c2 = u & 127;
        const float* src = (o < 32) ? (Wk + o*IC_ + 2*c2) : (Wv + (o-32)*IC_ + 2*c2);
        float2 v = *(const float2*)src;
        Wsm[o*PW + c2] = pk_bf16x2(v.y, v.x);
    }

    auto pref = [&](int ks, float* dstbuf) {
        const float* src = img + ((long)b*IC_ + ks*64)*L_ + l0;
        uint32_t dstb = smem_u32(dstbuf);
        #pragma unroll
        for (int t = 0; t < 16; t++) {
            int u = tid + t*256;
            int c = u >> 6, col = (u & 63) * 4;
            cp16(dstb + (c*PI + col)*4, src + (long)c*L_ + col);
        }
        CP_COMMIT();
    };
    pref(0, img0);

    float C[4][4][4];
    #pragma unroll
    for (int mt = 0; mt < 4; mt++) {
        const float* bias = (mt < 2) ? bk : bv;
        int ob = (mt & 1) * 16;
        float blo = bias[ob + g], bhi = bias[ob + 8 + g];
        #pragma unroll
        for (int nt = 0; nt < 4; nt++) {
            C[mt][nt][0] = C[mt][nt][1] = blo;
            C[mt][nt][2] = C[mt][nt][3] = bhi;
        }
    }
    __syncthreads();

    int lw = w * 32;
    for (int ks = 0; ks < 4; ks++) {
        if (ks < 3) { pref(ks + 1, (ks & 1) ? img0 : img1); CP_WAIT1(); }
        else CP_WAIT0();
        __syncthreads();
        const float* I = (ks & 1) ? img1 : img0;
        #pragma unroll
        for (int kk = 0; kk < 4; kk++) {
            uint32_t A[4][4];
            #pragma unroll
            for (int mt = 0; mt < 4; mt++) {
                const uint32_t* wp = Wsm + (mt*16)*PW + ks*32 + kk*8;
                A[mt][0] = wp[ g   *PW + q];
                A[mt][1] = wp[(g+8)*PW + q];
                A[mt][2] = wp[ g   *PW + q + 4];
                A[mt][3] = wp[(g+8)*PW + q + 4];
            }
            uint32_t Bf[4][2];
            #pragma unroll
            for (int nt = 0; nt < 4; nt++) {
                int l = lw + nt*8 + g;
                const float* r0 = I + (kk*16 + 2*q    )*PI + l;
                const float* r1 = I + (kk*16 + 2*q + 8)*PI + l;
                Bf[nt][0] = pk_bf16x2(r0[PI], r0[0]);
                Bf[nt][1] = pk_bf16x2(r1[PI], r1[0]);
            }
            #pragma unroll
            for (int mt = 0; mt < 4; mt++)
                #pragma unroll
                for (int nt = 0; nt < 4; nt++)
                    mma_bf16(C[mt][nt], A[mt], Bf[nt][0], Bf[nt][1]);
        }
        __syncthreads();
    }

    bool odd = (g & 1);
    int sA = 8*q + (g >> 1), sB = sA + 4;
    #pragma unroll
    for (int mt = 0; mt < 2; mt++)
        #pragma unroll
        for (int nt = 0; nt < 4; nt++) {
            float* c = C[mt][nt];
            float t0 = __shfl_sync(~0u, c[0], sA), t1 = __shfl_sync(~0u, c[1], sA);
            float t2 = __shfl_sync(~0u, c[0], sB), t3 = __shfl_sync(~0u, c[1], sB);
            float t4 = __shfl_sync(~0u, c[2], sA), t5 = __shfl_sync(~0u, c[3], sA);
            float t6 = __shfl_sync(~0u, c[2], sB), t7 = __shfl_sync(~0u, c[3], sB);
            float lo0 = odd ? t1 : t0, hi0 = odd ? t3 : t2;
            float lo1 = odd ? t5 : t4, hi1 = odd ? t7 : t6;
            long l = (long)b*L_ + l0 + lw + nt*8 + g;
            g_Kb[l*16 + mt*8 + q    ] = pk_bf16x2(hi0, lo0);
            g_Kb[l*16 + mt*8 + 4 + q] = pk_bf16x2(hi1, lo1);
        }
    #pragma unroll
    for (int mt = 2; mt < 4; mt++)
        #pragma unroll
        for (int nt = 0; nt < 4; nt++) {
            int c = (mt - 2)*16 + g;
            long base = ((long)b*GC_ + c)*L_ + l0 + lw + nt*8 + 2*q;
            *(float2*)(g_VTc + base)         = make_float2(C[mt][nt][0], C[mt][nt][1]);
            *(float2*)(g_VTc + base + 8*L_)  = make_float2(C[mt][nt][2], C[mt][nt][3]);
        }
}

// ===========================================================================
// Kernel 3: stats, 512 threads (16 warps = 4/SMSP).
// Warp pair (wp, wp+8) owns the same 32 l-rows, splits the n j-loop.
// ===========================================================================
#define QP 20

__global__ __launch_bounds__(512, 1) void k_stats_mma()
{
    __shared__ __align__(16) uint32_t Qs[2][128*QP];
    __shared__ float dS[2][256];
    __shared__ float dinvS[256];
    int tid = threadIdx.x, w = tid >> 5, lane = tid & 31;
    int wp = w & 7, wh = w >> 3;
    int q = lane & 3, g = lane >> 2;
    int b = blockIdx.x >> 4, l0 = (blockIdx.x & 15) * 256;
    uint32_t qs_b = smem_u32(Qs);

    uint32_t A[2][2][4];
    #pragma unroll
    for (int mt = 0; mt < 2; mt++) {
        const uint32_t* kp = g_Kb + ((long)b*L_ + l0 + wp*32 + mt*16)*16;
        #pragma unroll
        for (int kk = 0; kk < 2; kk++) {
            A[mt][kk][0] = kp[ g   *16 + 8*kk + q    ];
            A[mt][kk][1] = kp[(g+8)*16 + 8*kk + q    ];
            A[mt][kk][2] = kp[ g   *16 + 8*kk + q + 4];
            A[mt][kk][3] = kp[(g+8)*16 + 8*kk + q + 4];
        }
    }

    auto prefetch = [&](int nc, int buf) {
        const uint32_t* src = g_Qb + ((long)b*N_ + nc*128)*16;
        int r = tid >> 2, t = tid & 3;
        cp16(qs_b + (buf*128*QP + r*QP + 4*t)*4, src + r*16 + 4*t);
        CP_COMMIT();
    };
    prefetch(0, 0);

    float d[2][2] = {{0.f,0.f},{0.f,0.f}};
    int j0 = wh * 8;
    for (int nc = 0; nc < 32; nc++) {
        if (nc < 31) { prefetch(nc + 1, (nc + 1) & 1); CP_WAIT1(); }
        else CP_WAIT0();
        __syncthreads();
        const uint32_t* Q = &Qs[nc & 1][0];
        #pragma unroll 4
        for (int jj = 0; jj < 8; jj++) {
            int j = j0 + jj;
            const uint32_t* bp = &Q[(g + 8*j)*QP + q];
            uint32_t b00 = bp[0], b01 = bp[4];
            uint32_t b10 = bp[8], b11 = bp[12];
            #pragma unroll
            for (int mt = 0; mt < 2; mt++) {
                float c[4] = {0.f, 0.f, 0.f, 0.f};
                mma_bf16(c, A[mt][0], b00, b01);
                mma_bf16(c, A[mt][1], b10, b11);
                d[mt][0] += ex2f(c[0]) + ex2f(c[1]);
                d[mt][1] += ex2f(c[2]) + ex2f(c[3]);
            }
        }
        __syncthreads();
    }
    #pragma unroll
    for (int mt = 0; mt < 2; mt++) {
        #pragma unroll
        for (int h = 0; h < 2; h++) {
            float dv = d[mt][h];
            dv += __shfl_xor_sync(~0u, dv, 1);
            dv += __shfl_xor_sync(~0u, dv, 2);
            if (q == 0) dS[wh][wp*32 + mt*16 + h*8 + g] = dv;
        }
    }
    __syncthreads();
    if (tid < 256) dinvS[tid] = 1.0f / (dS[0][tid] + dS[1][tid]);
    __syncthreads();

    // V' production: channel-major read, pack pairs over l, coalesced write
    uint32_t* dst = g_Vb + ((long)b*GC_)*(L_/2) + (l0 >> 1);
    const float* vsrc = g_VTc + ((long)b*GC_)*L_ + l0;
    #pragma unroll
    for (int t = 0; t < 8; t++) {
        int u = tid + t*512;
        int c = u >> 7, l2 = u & 127;
        float2 v = *(const float2*)(vsrc + (long)c*L_ + 2*l2);
        dst[(long)c*(L_/2) + l2] =
            pk_bf16x2(v.y * dinvS[2*l2 + 1], v.x * dinvS[2*l2]);
    }
}

// ===========================================================================
// Kernel 4: final, 512 threads (16 warps = 4/SMSP).
// Warp pair (wp, wp+8) owns the same 32 n-rows, splits the l s-loop.
// Partial msg combined via smem before GEMM3 epilogue.
// ===========================================================================
#define KP 20
#define VP 68
#define SH_WORDS (2*128*KP + 2*32*VP)   // 9472 >= 256*36 = 9216 (msgP reuse)

__global__ __launch_bounds__(512, 1) void k_final_mma(
    const float* __restrict__ graph, const float* __restrict__ Wc,
    const float* __restrict__ bc, float* __restrict__ out)
{
    __shared__ __align__(16) uint32_t SH[SH_WORDS];
    __shared__ uint32_t Wb[32*17];
    int tid = threadIdx.x, w = tid >> 5, lane = tid & 31;
    int wp = w & 7, wh = w >> 3;
    int q = lane & 3, g = lane >> 2;
    int b = blockIdx.x >> 4, n0 = (blockIdx.x & 15) * 256;
    uint32_t sh_b = smem_u32(SH);
    uint32_t vb_off = 2*128*KP;   // Vbs starts here (word offset)

    uint32_t A[2][2][4];
    #pragma unroll
    for (int mt = 0; mt < 2; mt++) {
        const uint32_t* qp = g_Qb + ((long)b*N_ + n0 + wp*32 + mt*16)*16;
        #pragma unroll
        for (int kk = 0; kk < 2; kk++) {
            A[mt][kk][0] = qp[ g   *16 + 8*kk + q    ];
            A[mt][kk][1] = qp[(g+8)*16 + 8*kk + q    ];
            A[mt][kk][2] = qp[ g   *16 + 8*kk + q + 4];
            A[mt][kk][3] = qp[(g+8)*16 + 8*kk + q + 4];
        }
    }
    for (int i = tid; i < 32*16; i += 512) {
        int o = i >> 4, c2 = i & 15;
        Wb[o*17 + c2] = pk_bf16x2(Wc[o*32 + 2*c2 + 1], Wc[o*32 + 2*c2]);
    }

    const uint32_t* vbsrc = g_Vb + ((long)b*GC_)*(L_/2);
    auto prefetch = [&](int lc, int buf) {
        const uint32_t* ksrc = g_Kb + ((long)b*L_ + lc*128)*16;
        {
            int r = tid >> 2, t = tid & 3;
            cp16(sh_b + (buf*128*KP + r*KP + 4*t)*4, ksrc + r*16 + 4*t);
        }
        {
            int c = tid >> 4, t2 = tid & 15;
            cp16(sh_b + (vb_off + buf*32*VP + c*VP + 4*t2)*4,
                 vbsrc + (long)c*(L_/2) + lc*64 + 4*t2);
        }
        CP_COMMIT();
    };
    prefetch(0, 0);

    float mc[2][4][4];
    #pragma unroll
    for (int mt = 0; mt < 2; mt++)
        #pragma unroll
        for (int cf = 0; cf < 4; cf++)
            #pragma unroll
            for (int x = 0; x < 4; x++) mc[mt][cf][x] = 0.f;

    int s0 = wh * 4;
    for (int lc = 0; lc < 32; lc++) {
        if (lc < 31) { prefetch(lc + 1, (lc + 1) & 1); CP_WAIT1(); }
        else CP_WAIT0();
        __syncthreads();
        const uint32_t* K = SH + (lc & 1)*128*KP;
        const uint32_t* V = SH + vb_off + (lc & 1)*32*VP;

        #pragma unroll 2
        for (int ss = 0; ss < 4; ss++) {
            int s = s0 + ss;
            const uint32_t* bpa = &K[(g + 16*s    )*KP + q];
            const uint32_t* bpb = &K[(g + 16*s + 8)*KP + q];
            uint32_t ba00 = bpa[0], ba01 = bpa[4], ba10 = bpa[8], ba11 = bpa[12];
            uint32_t bb00 = bpb[0], bb01 = bpb[4], bb10 = bpb[8], bb11 = bpb[12];
            uint32_t vb0[4], vb1[4];
            #pragma unroll
            for (int cf = 0; cf < 4; cf++) {
                vb0[cf] = V[(g + 8*cf)*VP + 8*s + q    ];
                vb1[cf] = V[(g + 8*cf)*VP + 8*s + q + 4];
            }
            #pragma unroll
            for (int mt = 0; mt < 2; mt++) {
                float c0[4] = {0.f,0.f,0.f,0.f};
                float c1[4] = {0.f,0.f,0.f,0.f};
                mma_bf16(c0, A[mt][0], ba00, ba01);
                mma_bf16(c0, A[mt][1], ba10, ba11);
                mma_bf16(c1, A[mt][0], bb00, bb01);
                mma_bf16(c1, A[mt][1], bb10, bb11);
                uint32_t A2[4];
                A2[0] = pk_bf16x2(ex2f(c0[1]), ex2f(c0[0]));
                A2[1] = pk_bf16x2(ex2f(c0[3]), ex2f(c0[2]));
                A2[2] = pk_bf16x2(ex2f(c1[1]), ex2f(c1[0]));
                A2[3] = pk_bf16x2(ex2f(c1[3]), ex2f(c1[2]));
                #pragma unroll
                for (int cf = 0; cf < 4; cf++)
                    mma_bf16(mc[mt][cf], A2, vb0[cf], vb1[cf]);
            }
        }
        __syncthreads();
    }

    // combine warp-pair partials via smem (reuse SH as msgP[256][36])
    float* msgP = (float*)SH;
    if (wh == 1) {
        #pragma unroll
        for (int mt = 0; mt < 2; mt++) {
            int rb = wp*32 + mt*16;
            #pragma unroll
            for (int cf = 0; cf < 4; cf++) {
                int col = cf*8 + 2*q;
                *(float2*)&msgP[(rb + g    )*36 + col] =
                    make_float2(mc[mt][cf][0], mc[mt][cf][1]);
                *(float2*)&msgP[(rb + g + 8)*36 + col] =
                    make_float2(mc[mt][cf][2], mc[mt][cf][3]);
            }
        }
    }
    __syncthreads();

    if (wh == 0) {
        #pragma unroll
        for (int mt = 0; mt < 2; mt++) {
            int rb = wp*32 + mt*16;
            #pragma unroll
            for (int cf = 0; cf < 4; cf++) {
                int col = cf*8 + 2*q;
                float2 p0 = *(const float2*)&msgP[(rb + g    )*36 + col];
                float2 p1 = *(const float2*)&msgP[(rb + g + 8)*36 + col];
                mc[mt][cf][0] += p0.x; mc[mt][cf][1] += p0.y;
                mc[mt][cf][2] += p1.x; mc[mt][cf][3] += p1.y;
            }
        }
        // Epilogue GEMM3: out = graph + bc + msg·Wcᵀ
        #pragma unroll
        for (int mt = 0; mt < 2; mt++) {
            uint32_t A3[2][4];
            #pragma unroll
            for (int t = 0; t < 2; t++) {
                A3[t][0] = pk_bf16x2(mc[mt][2*t  ][1], mc[mt][2*t  ][0]);
                A3[t][1] = pk_bf16x2(mc[mt][2*t  ][3], mc[mt][2*t  ][2]);
                A3[t][2] = pk_bf16x2(mc[mt][2*t+1][1], mc[mt][2*t+1][0]);
                A3[t][3] = pk_bf16x2(mc[mt][2*t+1][3], mc[mt][2*t+1][2]);
            }
            long nbase = (long)b*N_ + n0 + wp*32 + mt*16;
            const float* gp = graph + nbase*32;
            float* op = out + nbase*32;
            #pragma unroll
            for (int of = 0; of < 4; of++) {
                int col = 8*of + 2*q;
                float bc0 = bc[col], bc1 = bc[col + 1];
                float2 gr0 = *(const float2*)(gp + g*32 + col);
                float2 gr1 = *(const float2*)(gp + (g + 8)*32 + col);
                float c[4] = { gr0.x + bc0, gr0.y + bc1, gr1.x + bc0, gr1.y + bc1 };
                #pragma unroll
                for (int t = 0; t < 2; t++) {
                    uint32_t b0 = Wb[(g + 8*of)*17 + 8*t + q    ];
                    uint32_t b1 = Wb[(g + 8*of)*17 + 8*t + q + 4];
                    mma_bf16(c, A3[t], b0, b1);
                }
                *(float2*)(op + g*32 + col)       = make_float2(c[0], c[1]);
                *(float2*)(op + (g + 8)*32 + col) = make_float2(c[2], c[3]);
            }
        }
    }
}

// ===========================================================================
extern "C" void kernel_launch(void* const* d_in, const int* in_sizes, int n_in,
                              void* d_out, int out_size)
{
    const float* graph = (const float*)d_in[0];
    const float* img   = (const float*)d_in[1];
    const float* Wq    = (const float*)d_in[2];
    const float* bq    = (const float*)d_in[3];
    const float* Wk    = (const float*)d_in[4];
    const float* bk    = (const float*)d_in[5];
    const float* Wv    = (const float*)d_in[6];
    const float* bv    = (const float*)d_in[7];
    const float* Wc    = (const float*)d_in[8];
    const float* bc    = (const float*)d_in[9];
    float* out = (float*)d_out;

    size_t proj_smem = (64*PW + 2*64*PI) * sizeof(uint32_t);
    static int attr_set = 0;
    if (!attr_set) {
        cudaFuncSetAttribute(k_proj_kv_mma,
                             cudaFuncAttributeMaxDynamicSharedMemorySize,
                             (int)proj_smem);
        attr_set = 1;
    }

    k_proj_q     <<<B_*(N_/64), 256>>>(graph, Wq, bq);
    k_proj_kv_mma<<<B_*(L_/256), 256, proj_smem>>>(img, Wk, bk, Wv, bv);
    k_stats_mma  <<<B_*(L_/256), 512>>>();
    k_final_mma  <<<B_*(N_/256), 512>>>(graph, Wc, bc, out);
}